// round 1
// baseline (speedup 1.0000x reference)
#include <cuda_runtime.h>
#include <cstddef>

#define N_BOX 1024
#define HF 192          // feature H = W
#define CF 64           // feature channels
#define S 32            // crop size
#define PS 34           // padded crop size (zero border for SAME convs)
#define CH 64           // conv channels
#define OUTW 30         // VALID conv output

// -------- static scratch (no allocation allowed) --------
__device__ float g_buf0[(size_t)N_BOX * PS * PS * CH];  // crop, padded
__device__ float g_buf1[(size_t)N_BOX * PS * PS * CH];  // conv1 out, padded
__device__ float g_buf2[(size_t)N_BOX * S * S * CH];    // conv2 out, unpadded

// ============================================================
// Kernel 1: crop_and_resize -> g_buf0 (padded, zero border)
// grid (PS, N_BOX), block 256
// ============================================================
__global__ __launch_bounds__(256) void crop_kernel(
    const float* __restrict__ feat,
    const float* __restrict__ boxes,
    const int*   __restrict__ box_ids)
{
    int n  = blockIdx.y;
    int py = blockIdx.x;
    int t  = threadIdx.x;
    float* out = g_buf0 + ((size_t)(n * PS + py)) * PS * CH;

    if (py == 0 || py == PS - 1) {
        for (int i = t; i < PS * CH; i += 256) out[i] = 0.f;
        return;
    }
    int y = py - 1;
    float y1 = boxes[n * 4 + 0], x1 = boxes[n * 4 + 1];
    float y2 = boxes[n * 4 + 2], x2 = boxes[n * 4 + 3];
    int b = box_ids[n];

    float ty  = (float)y / (float)(S - 1);
    float ys  = (y1 + ty * (y2 - y1)) * (float)(HF - 1);
    float y0f = floorf(ys);
    y0f = fminf(fmaxf(y0f, 0.f), (float)(HF - 1));
    float wy  = ys - y0f;
    int y0i = (int)y0f;
    int y1i = min(y0i + 1, HF - 1);

    const float* frow0 = feat + ((size_t)(b * HF + y0i)) * HF * CF;
    const float* frow1 = feat + ((size_t)(b * HF + y1i)) * HF * CF;

    for (int i = t; i < PS * CH; i += 256) {
        int px = i >> 6;
        int c  = i & 63;
        if (px == 0 || px == PS - 1) { out[i] = 0.f; continue; }
        int x = px - 1;
        float tx  = (float)x / (float)(S - 1);
        float xs  = (x1 + tx * (x2 - x1)) * (float)(HF - 1);
        float x0f = floorf(xs);
        x0f = fminf(fmaxf(x0f, 0.f), (float)(HF - 1));
        float wx  = xs - x0f;
        int x0i = (int)x0f;
        int x1i = min(x0i + 1, HF - 1);

        float v00 = frow0[x0i * CF + c];
        float v01 = frow0[x1i * CF + c];
        float v10 = frow1[x0i * CF + c];
        float v11 = frow1[x1i * CF + c];
        float top = v00 * (1.f - wx) + v01 * wx;
        float bot = v10 * (1.f - wx) + v11 * wx;
        out[i] = top * (1.f - wy) + bot * wy;
    }
}

// ============================================================
// Kernel 2: zero the border of g_buf1 (conv1 writes interior only)
// grid (N_BOX), block 256
// ============================================================
__global__ __launch_bounds__(256) void zero_border_kernel(float* __restrict__ buf)
{
    int n = blockIdx.x;
    int t = threadIdx.x;
    const int TOT = (2 * PS + 2 * S) * CH;  // 132 * 64
    for (int i = t; i < TOT; i += 256) {
        int c = i & 63;
        int j = i >> 6;
        int py, px;
        if (j < PS)               { py = 0;                  px = j; }
        else if (j < 2 * PS)      { py = PS - 1;             px = j - PS; }
        else if (j < 2 * PS + S)  { py = j - 2 * PS + 1;     px = 0; }
        else                      { py = j - (2 * PS + S) + 1; px = PS - 1; }
        buf[((size_t)(n * PS + py) * PS + px) * CH + c] = 0.f;
    }
}

// ============================================================
// Kernel 3/4: 3x3 conv (64->64) + bias + ReLU
// Input: padded [N][34][34][64].  PAD_OUT: write into padded layout (interior)
// else unpadded [N][32][32][64].
// grid (8 row-tiles, N_BOX), block 256 = 32 x-cols * 8 co-groups.
// smem: wsm[9][32][64] (ci-chunked) + slab[32][6][34] (ci-major, transposed)
// ============================================================
#define CONV_SMEM_FLOATS (9 * 32 * 64 + 32 * 6 * 34)       // 18432 + 6528
#define CONV_SMEM_BYTES  (CONV_SMEM_FLOATS * 4)            // 99840

template <bool PAD_OUT>
__global__ __launch_bounds__(256) void conv3x3_kernel(
    const float* __restrict__ in,    // padded input
    float*       __restrict__ outbuf,
    const float* __restrict__ w,     // [3][3][64][64]
    const float* __restrict__ bias)
{
    extern __shared__ float sm[];
    float* wsm  = sm;                // [9][32][64]
    float* slab = sm + 9 * 32 * 64;  // [32][6][34], stride 204 per ci

    int n    = blockIdx.y;
    int tile = blockIdx.x;           // 0..7 -> output rows tile*4 .. tile*4+3
    int t    = threadIdx.x;
    int x    = t & 31;
    int g    = t >> 5;               // co group, co = g*8..g*8+7

    float acc[4][8];
#pragma unroll
    for (int r = 0; r < 4; r++)
#pragma unroll
        for (int o = 0; o < 8; o++) acc[r][o] = 0.f;

    const float4* in4 = (const float4*)in;
    const float4* w4g = (const float4*)w;

    for (int cb = 0; cb < 2; cb++) {
        // ---- load input slab: rows tile*4 .. tile*4+5, all 34 px, 32 ci, transposed
        for (int idx = t; idx < 6 * 34 * 8; idx += 256) {
            int ci4 = idx & 7;
            int rem = idx >> 3;
            int px  = rem % 34;
            int row = rem / 34;
            float4 v = in4[((size_t)(n * PS + tile * 4 + row) * PS + px) * (CH / 4)
                           + cb * 8 + ci4];
            int cbse = ci4 * 4;
            slab[(cbse + 0) * 204 + row * 34 + px] = v.x;
            slab[(cbse + 1) * 204 + row * 34 + px] = v.y;
            slab[(cbse + 2) * 204 + row * 34 + px] = v.z;
            slab[(cbse + 3) * 204 + row * 34 + px] = v.w;
        }
        // ---- load weight chunk [9][32][64]
        for (int idx = t; idx < 9 * 32 * 16; idx += 256) {
            int co4 = idx & 15;
            int rem = idx >> 4;
            int ci  = rem & 31;
            int p   = rem >> 5;
            ((float4*)wsm)[(p * 32 + ci) * 16 + co4] =
                w4g[((size_t)(p * 64 + cb * 32 + ci)) * 16 + co4];
        }
        __syncthreads();

#pragma unroll
        for (int p = 0; p < 9; p++) {
            const int ky = p / 3, kx = p % 3;
            const float*  srow = slab + ky * 34 + x + kx;
            const float4* wrow = ((const float4*)wsm) + p * 32 * 16 + g * 2;
#pragma unroll 4
            for (int ci = 0; ci < 32; ci++) {
                float4 wa = wrow[ci * 16];
                float4 wb = wrow[ci * 16 + 1];
                const float* sp = srow + ci * 204;
#pragma unroll
                for (int r = 0; r < 4; r++) {
                    float s = sp[r * 34];
                    acc[r][0] += s * wa.x; acc[r][1] += s * wa.y;
                    acc[r][2] += s * wa.z; acc[r][3] += s * wa.w;
                    acc[r][4] += s * wb.x; acc[r][5] += s * wb.y;
                    acc[r][6] += s * wb.z; acc[r][7] += s * wb.w;
                }
            }
        }
        __syncthreads();
    }

    int co0 = g * 8;
    float bv[8];
#pragma unroll
    for (int o = 0; o < 8; o++) bv[o] = __ldg(&bias[co0 + o]);

#pragma unroll
    for (int r = 0; r < 4; r++) {
        int y = tile * 4 + r;
        float* op;
        if (PAD_OUT)
            op = outbuf + (((size_t)(n * PS + y + 1) * PS) + x + 1) * CH + co0;
        else
            op = outbuf + (((size_t)(n * S + y) * S) + x) * CH + co0;
        float4 o0, o1;
        o0.x = fmaxf(acc[r][0] + bv[0], 0.f);
        o0.y = fmaxf(acc[r][1] + bv[1], 0.f);
        o0.z = fmaxf(acc[r][2] + bv[2], 0.f);
        o0.w = fmaxf(acc[r][3] + bv[3], 0.f);
        o1.x = fmaxf(acc[r][4] + bv[4], 0.f);
        o1.y = fmaxf(acc[r][5] + bv[5], 0.f);
        o1.z = fmaxf(acc[r][6] + bv[6], 0.f);
        o1.w = fmaxf(acc[r][7] + bv[7], 0.f);
        ((float4*)op)[0] = o0;
        ((float4*)op)[1] = o1;
    }
}

// ============================================================
// Kernel 5: 3x3 VALID conv, ONLY the selected class channel + channel select
// grid (N_BOX), block 256 = 32 x * 8 ci-groups (partial-sum reduction)
// ============================================================
__global__ __launch_bounds__(256) void outconv_kernel(
    const float* __restrict__ buf2,  // [N][32][32][64]
    const float* __restrict__ ow,    // [3][3][64][3]
    const float* __restrict__ ob,    // [3]
    const int*   __restrict__ cls,
    float*       __restrict__ out)   // [N][30][30]
{
    __shared__ float ws[576];            // [9][64] weight slice for this class
    __shared__ float insm[64 * 3 * 32];  // [ci][ry][x]
    __shared__ float red[8][32];

    int n = blockIdx.x;
    int t = threadIdx.x;
    int k = __ldg(&cls[n]);

    for (int i = t; i < 576; i += 256) ws[i] = ow[i * 3 + k];
    float bias = __ldg(&ob[k]);

    int ox  = t & 31;
    int grp = t >> 5;
    const float4* b2 = (const float4*)buf2;

    for (int oy = 0; oy < OUTW; oy++) {
        __syncthreads();  // protect prev-iter insm/red reads, and ws on iter 0
        for (int idx = t; idx < 3 * 32 * 16; idx += 256) {
            int ci4 = idx & 15;
            int rem = idx >> 4;
            int px  = rem & 31;
            int ry  = rem >> 5;
            float4 v = b2[((size_t)(n * S + oy + ry) * S + px) * 16 + ci4];
            int cb = ci4 * 4;
            insm[(cb + 0) * 96 + ry * 32 + px] = v.x;
            insm[(cb + 1) * 96 + ry * 32 + px] = v.y;
            insm[(cb + 2) * 96 + ry * 32 + px] = v.z;
            insm[(cb + 3) * 96 + ry * 32 + px] = v.w;
        }
        __syncthreads();

        float part = 0.f;
        if (ox < OUTW) {
#pragma unroll
            for (int p = 0; p < 9; p++) {
                const int ky = p / 3, kx = p % 3;
#pragma unroll
                for (int ci = 0; ci < 8; ci++) {
                    int cig = grp * 8 + ci;
                    part += insm[cig * 96 + ky * 32 + ox + kx] * ws[p * 64 + cig];
                }
            }
        }
        red[grp][ox] = part;
        __syncthreads();
        if (grp == 0 && ox < OUTW) {
            float ssum = bias;
#pragma unroll
            for (int q = 0; q < 8; q++) ssum += red[q][ox];
            out[(size_t)n * (OUTW * OUTW) + oy * OUTW + ox] = ssum;
        }
    }
}

// ============================================================
// Launch
// ============================================================
extern "C" void kernel_launch(void* const* d_in, const int* in_sizes, int n_in,
                              void* d_out, int out_size)
{
    const float* features = (const float*)d_in[0];
    const float* boxes    = (const float*)d_in[1];
    const int*   box_ids  = (const int*)d_in[2];
    const int*   cls      = (const int*)d_in[3];
    const float* w1       = (const float*)d_in[4];
    const float* b1       = (const float*)d_in[5];
    const float* w2       = (const float*)d_in[6];
    const float* b2       = (const float*)d_in[7];
    const float* ow       = (const float*)d_in[8];
    const float* ob       = (const float*)d_in[9];
    float* out = (float*)d_out;

    // capture-safe (not stream-ordered), idempotent
    cudaFuncSetAttribute(conv3x3_kernel<true>,
                         cudaFuncAttributeMaxDynamicSharedMemorySize, CONV_SMEM_BYTES);
    cudaFuncSetAttribute(conv3x3_kernel<false>,
                         cudaFuncAttributeMaxDynamicSharedMemorySize, CONV_SMEM_BYTES);

    void *p0 = nullptr, *p1 = nullptr, *p2 = nullptr;
    cudaGetSymbolAddress(&p0, g_buf0);
    cudaGetSymbolAddress(&p1, g_buf1);
    cudaGetSymbolAddress(&p2, g_buf2);

    crop_kernel<<<dim3(PS, N_BOX), 256>>>(features, boxes, box_ids);
    zero_border_kernel<<<N_BOX, 256>>>((float*)p1);
    conv3x3_kernel<true><<<dim3(8, N_BOX), 256, CONV_SMEM_BYTES>>>(
        (const float*)p0, (float*)p1, w1, b1);
    conv3x3_kernel<false><<<dim3(8, N_BOX), 256, CONV_SMEM_BYTES>>>(
        (const float*)p1, (float*)p2, w2, b2);
    outconv_kernel<<<N_BOX, 256>>>((const float*)p2, ow, ob, cls, out);
}